// round 15
// baseline (speedup 1.0000x reference)
#include <cuda_runtime.h>
#include <cuda_bf16.h>
#include <cuda_fp16.h>
#include <cstdint>

// Problem constants
#define BB 2
#define NN 2048
#define EE 768
#define HH 12
#define DD 64
#define E3 (3*EE)
#define MM (BB*NN)   // 4096 rows per modality

// 8 * log2(e): folds softmax exp->exp2 into the Q scale
#define QSCALE 11.541560327111707f

#define NQKV ((size_t)E3 * EE)
#define NPROJ ((size_t)EE * EE)
#define QSZ ((size_t)BB * HH * NN * DD)

// tcgen05 is architecture-SPECIFIC (sm_103a). Non-specific pass -> mma.sync.
#if defined(__CUDA_ARCH_FEAT_SM103_ALL) || defined(__CUDA_ARCH_FEAT_SM100_ALL) || \
    defined(__CUDA_ARCH_FEAT_SM101_ALL) || \
    (defined(__CUDA_ARCH_SPECIFIC__) && (__CUDA_ARCH_SPECIFIC__ >= 1000)) || \
    (defined(__CUDA_ARCH_FAMILY_SPECIFIC__) && (__CUDA_ARCH_FAMILY_SPECIFIC__ >= 1000))
#define HAS_TCGEN05 1
#else
#define HAS_TCGEN05 0
#endif

// ------------------------------ helpers ------------------------------------
__device__ __forceinline__ uint32_t smem_u32(const void* p) {
    uint32_t a;
    asm("{ .reg .u64 t; cvta.to.shared.u64 t, %1; cvt.u32.u64 %0, t; }"
        : "=r"(a) : "l"(p));
    return a;
}
__device__ __forceinline__ void ldsm4(uint32_t* r, uint32_t addr) {
    asm volatile("ldmatrix.sync.aligned.m8n8.x4.shared.b16 {%0,%1,%2,%3}, [%4];"
        : "=r"(r[0]), "=r"(r[1]), "=r"(r[2]), "=r"(r[3]) : "r"(addr));
}
__device__ __forceinline__ void ldsm4t(uint32_t* r, uint32_t addr) {
    asm volatile("ldmatrix.sync.aligned.m8n8.x4.trans.shared.b16 {%0,%1,%2,%3}, [%4];"
        : "=r"(r[0]), "=r"(r[1]), "=r"(r[2]), "=r"(r[3]) : "r"(addr));
}
__device__ __forceinline__ void mma16816(float* c, const uint32_t* a, const uint32_t* b) {
    asm volatile("mma.sync.aligned.m16n8k16.row.col.f32.bf16.bf16.f32 "
        "{%0,%1,%2,%3}, {%4,%5,%6,%7}, {%8,%9}, {%0,%1,%2,%3};"
        : "+f"(c[0]), "+f"(c[1]), "+f"(c[2]), "+f"(c[3])
        : "r"(a[0]), "r"(a[1]), "r"(a[2]), "r"(a[3]), "r"(b[0]), "r"(b[1]));
}
__device__ __forceinline__ void mma16816h(float* c, const uint32_t* a, const uint32_t* b) {
    asm volatile("mma.sync.aligned.m16n8k16.row.col.f32.f16.f16.f32 "
        "{%0,%1,%2,%3}, {%4,%5,%6,%7}, {%8,%9}, {%0,%1,%2,%3};"
        : "+f"(c[0]), "+f"(c[1]), "+f"(c[2]), "+f"(c[3])
        : "r"(a[0]), "r"(a[1]), "r"(a[2]), "r"(a[3]), "r"(b[0]), "r"(b[1]));
}
__device__ __forceinline__ float ex2f(float x) {
    float y; asm("ex2.approx.f32 %0, %1;" : "=f"(y) : "f"(x)); return y;
}
__device__ __forceinline__ uint32_t cvth2(float hi, float lo) {
    uint32_t r; asm("cvt.rn.f16x2.f32 %0, %1, %2;" : "=r"(r) : "f"(hi), "f"(lo));
    return r;
}
__device__ __forceinline__ void cpa16(uint32_t dst, const void* src) {
    asm volatile("cp.async.cg.shared.global [%0], [%1], 16;" :: "r"(dst), "l"(src));
}
#define CP_COMMIT() asm volatile("cp.async.commit_group;" ::: "memory")
#define CP_WAIT(n)  asm volatile("cp.async.wait_group %0;" :: "n"(n) : "memory")

__device__ __forceinline__ void split_st(__nv_bfloat16* hi, __nv_bfloat16* lo,
                                         size_t idx, float v) {
    __nv_bfloat16 h = __float2bfloat16(v);
    hi[idx] = h;
    lo[idx] = __float2bfloat16(v - __bfloat162float(h));
}

#if HAS_TCGEN05
__device__ __forceinline__ uint32_t elect_one() {
    uint32_t pred;
    asm volatile("{\n\t.reg .pred p;\n\telect.sync _|p, 0xFFFFFFFF;\n\t"
                 "selp.b32 %0, 1, 0, p;\n\t}" : "=r"(pred));
    return pred;
}
#define MBAR_INIT(a, c) \
    asm volatile("mbarrier.init.shared.b64 [%0], %1;" :: "r"(a), "r"(c) : "memory")
#define MBAR_WAIT(a, ph) do {                                                   \
    uint32_t _m = (a), _p = (ph), _d;                                           \
    asm volatile("{\n\t.reg .pred p;\n\t"                                       \
        "mbarrier.try_wait.parity.acquire.cta.shared::cta.b64 p, [%1], %2;\n\t" \
        "selp.b32 %0, 1, 0, p;\n\t}" : "=r"(_d) : "r"(_m), "r"(_p) : "memory"); \
    if (!_d) {                                                                  \
        asm volatile("{\n\t.reg .pred P1;\n\tWL_%=: \n\t"                       \
            "mbarrier.try_wait.parity.acquire.cta.shared::cta.b64 P1, [%0], %1, 0x989680;\n\t" \
            "@P1 bra.uni WD_%=;\n\tbra.uni WL_%=;\n\tWD_%=:\n\t}"               \
            :: "r"(_m), "r"(_p) : "memory");                                    \
    }                                                                           \
} while (0)
#define TC_ALLOC(sa, n) \
    asm volatile("tcgen05.alloc.cta_group::1.sync.aligned.shared::cta.b32 [%0], %1;" \
                 :: "r"(sa), "r"(n) : "memory")
#define TC_DEALLOC(t, n) \
    asm volatile("tcgen05.dealloc.cta_group::1.sync.aligned.b32 %0, %1;" :: "r"(t), "r"(n))
#define TC_RELINQ() \
    asm volatile("tcgen05.relinquish_alloc_permit.cta_group::1.sync.aligned;")
#define TC_COMMIT(mb) \
    asm volatile("tcgen05.commit.cta_group::1.mbarrier::arrive::one.shared::cluster.b64 [%0];" \
                 :: "r"(mb) : "memory")
#define TC_FENCE_AFTER() asm volatile("tcgen05.fence::after_thread_sync;" ::: "memory")
#define TC_WAIT_LD() asm volatile("tcgen05.wait::ld.sync.aligned;" ::: "memory")
#define FENCE_ASYNC() asm volatile("fence.proxy.async.shared::cta;" ::: "memory")
#define TC_LD_X32(r, ta) \
    asm volatile("tcgen05.ld.sync.aligned.32x32b.x32.b32 " \
        "{%0, %1, %2, %3, %4, %5, %6, %7, %8, %9, %10, %11, %12, %13, %14, %15, " \
        " %16, %17, %18, %19, %20, %21, %22, %23, %24, %25, %26, %27, %28, %29, %30, %31}, [%32];" \
        : "=r"((r)[0]),  "=r"((r)[1]),  "=r"((r)[2]),  "=r"((r)[3]),  \
          "=r"((r)[4]),  "=r"((r)[5]),  "=r"((r)[6]),  "=r"((r)[7]),  \
          "=r"((r)[8]),  "=r"((r)[9]),  "=r"((r)[10]), "=r"((r)[11]), \
          "=r"((r)[12]), "=r"((r)[13]), "=r"((r)[14]), "=r"((r)[15]), \
          "=r"((r)[16]), "=r"((r)[17]), "=r"((r)[18]), "=r"((r)[19]), \
          "=r"((r)[20]), "=r"((r)[21]), "=r"((r)[22]), "=r"((r)[23]), \
          "=r"((r)[24]), "=r"((r)[25]), "=r"((r)[26]), "=r"((r)[27]), \
          "=r"((r)[28]), "=r"((r)[29]), "=r"((r)[30]), "=r"((r)[31]) \
        : "r"(ta))

// SW64 smem descriptor: layout=SW64(4), version=1, SBO=32, LBO=1 (64B K-major rows)
static constexpr uint64_t DESC_BASE64 =
    (uint64_t(4) << 61) | (uint64_t(1) << 46) | (uint64_t(32) << 32) | (uint64_t(1) << 16);
#define MK_DESC64(a) (DESC_BASE64 | ((uint64_t)((a) >> 4) & 0x3FFF))

// cg1 bf16 SS MMA idesc: F32 acc | BF16 a | BF16 b | N=128 | M=128
static constexpr uint32_t GEMM_IDESC =
    (1u << 4) | (1u << 7) | (1u << 10) | ((128u / 8) << 17) | ((128u / 16) << 24);

__device__ __forceinline__ void mma_f16_ss(uint32_t d, uint64_t a, uint64_t b,
                                           uint32_t idesc, uint32_t en) {
    asm volatile("{\n\t.reg .pred p;\n\tsetp.ne.u32 p, %4, 0;\n\t"
        "tcgen05.mma.cta_group::1.kind::f16 [%0], %1, %2, %3, {%5,%5,%5,%5}, p;\n\t}"
        :: "r"(d), "l"(a), "l"(b), "r"(idesc), "r"(en), "r"(0u) : "memory");
}
#endif

// ---------------- scratch (device globals; DEVICE-SIDE refs only!) ---------
__device__ __align__(256) __nv_bfloat16 g_xn_hi[2*MM*EE],  g_xn_lo[2*MM*EE];
__device__ __align__(256) __nv_bfloat16 g_att_hi[2*MM*EE], g_att_lo[2*MM*EE];
__device__ __align__(256) __nv_bfloat16 g_w_hi[2*(E3+EE)*EE], g_w_lo[2*(E3+EE)*EE];
__device__ __align__(256) __nv_bfloat16 g_qhi[2*BB*HH*NN*DD], g_qlo[2*BB*HH*NN*DD];
__device__ __align__(256) __nv_bfloat16 g_khi[2*BB*HH*NN*DD], g_klo[2*BB*HH*NN*DD];
__device__ __align__(256) __half        g_v16[2*BB*HH*NN*DD];   // V: single fp16 plane

// ---------------- fused LayerNorm (both modalities) -------------------------
__global__ __launch_bounds__(256) void ln_fused(
        const float* __restrict__ x0, const float* __restrict__ x1,
        const float* __restrict__ g0, const float* __restrict__ b0,
        const float* __restrict__ g1, const float* __restrict__ b1) {
    int grow = blockIdx.x;
    int mz = grow >> 12;
    const float* x = mz ? x1 : x0;
    const float* g = mz ? g1 : g0;
    const float* bta = mz ? b1 : b0;
    const float* xr = x + (size_t)(grow & (MM - 1)) * EE;
    int t = threadIdx.x;
    float v0 = xr[t], v1 = xr[t + 256], v2 = xr[t + 512];
    float s  = v0 + v1 + v2;
    float sq = v0*v0 + v1*v1 + v2*v2;
    __shared__ float rs[8], rq[8];
    #pragma unroll
    for (int o = 16; o; o >>= 1) {
        s  += __shfl_xor_sync(0xffffffffu, s,  o);
        sq += __shfl_xor_sync(0xffffffffu, sq, o);
    }
    if ((t & 31) == 0) { rs[t >> 5] = s; rq[t >> 5] = sq; }
    __syncthreads();
    float S = 0.f, Q = 0.f;
    #pragma unroll
    for (int i = 0; i < 8; i++) { S += rs[i]; Q += rq[i]; }
    float mu  = S * (1.0f / EE);
    float var = Q * (1.0f / EE) - mu * mu;
    float inv = rsqrtf(var + 1e-5f);
    #pragma unroll
    for (int p = 0; p < 3; p++) {
        int c = t + p * 256;
        float v = (p == 0 ? v0 : p == 1 ? v1 : v2);
        float y = (v - mu) * inv * g[c] + bta[c];
        split_st(g_xn_hi, g_xn_lo, (size_t)grow * EE + c, y);
    }
}

// ---------------- fused weight split ----------------------------------------
__global__ __launch_bounds__(256) void split_fused(
        const float* __restrict__ wq0, const float* __restrict__ wp0,
        const float* __restrict__ wq1, const float* __restrict__ wp1) {
    size_t i = (size_t)blockIdx.x * 256 + threadIdx.x;
    float v;
    if (i < 2 * NQKV) {
        v = (i < NQKV) ? wq0[i] : wq1[i - NQKV];
    } else {
        size_t j = i - 2 * NQKV;
        if (j >= 2 * NPROJ) return;
        v = (j < NPROJ) ? wp0[j] : wp1[j - NPROJ];
    }
    split_st(g_w_hi, g_w_lo, i, v);
}

// ---------------- GEMM epilogue store ----------------------------------------
__device__ __forceinline__ void gemm_store(int mz, int gr, int gc, float accv,
        int mode, const float* __restrict__ bias,
        const float* __restrict__ resid, float* __restrict__ outp) {
    float val = accv + bias[gc];
    if (mode == 0) {
        int bI = gr >> 11, nI = gr & (NN - 1);
        int t3 = gc / 3;
        int s3 = gc - 3 * t3;
        int dd = t3 & 63;
        int hh = gc / 192;
        size_t idx = (size_t)mz * QSZ + ((size_t)(bI * HH + hh) * NN + nI) * DD + dd;
        if (s3 == 0)      split_st(g_qhi, g_qlo, idx, val * QSCALE);
        else if (s3 == 1) split_st(g_khi, g_klo, idx, val);
        else              g_v16[idx] = __float2half(val);
    } else {
        outp[(size_t)gr * EE + gc] = resid[(size_t)gr * EE + gc] + val;
    }
}

// ---------------- fused split-bf16 GEMM: 256x256 tiles (traffic /2) ----------
// 24 chunks of K=32 (SW64, validated), 2-stage cp.async pipeline, TMEM 512
// cols (full), 4 sub-block MMAs (2 row-blocks x 2 col-blocks), staged
// coalesced epilogue run 4x. 1 CTA/SM but L2-traffic-bound so that's fine.
#define PL64 16384                    // plane: 256 rows x 64B SW64
#define TSTG (4*PL64)                 // 65536 per stage (Ahi,Alo,Bhi,Blo)
#define GEMM_SMEM_HOST (1024 + 2*TSTG)  // 132096

#define KCH 32
#define NC (EE/KCH)                   // 24
#define GLD2 40
#define PLN2 (128*GLD2*2)
#define STG2 (4*PLN2)

__global__ __launch_bounds__(256) void gemm_fused(
        const float* __restrict__ bias0, const float* __restrict__ bias1,
        const float* __restrict__ resid0, const float* __restrict__ resid1,
        float* __restrict__ outp, int mode) {
    int tid = threadIdx.x;
    int mz = blockIdx.z;
    int m0 = blockIdx.y * 256, n0 = blockIdx.x * 256;

    const __nv_bfloat16* Ahi = (mode == 0 ? g_xn_hi : g_att_hi)
                               + (size_t)mz * MM * EE + (size_t)m0 * EE;
    const __nv_bfloat16* Alo = (mode == 0 ? g_xn_lo : g_att_lo)
                               + (size_t)mz * MM * EE + (size_t)m0 * EE;
    size_t bofs = (mode == 0) ? (size_t)mz * NQKV : 2 * NQKV + (size_t)mz * NPROJ;
    const __nv_bfloat16* Bhi = g_w_hi + bofs + (size_t)n0 * EE;
    const __nv_bfloat16* Blo = g_w_lo + bofs + (size_t)n0 * EE;
    const float* bias  = mz ? bias1 : bias0;
    const float* resid = mz ? resid1 : resid0;
    float* op = outp + (size_t)mz * MM * EE;

#if HAS_TCGEN05
    extern __shared__ char smraw[];
    uint32_t sbr = smem_u32(smraw);
    uint32_t sb  = (sbr + 1023u) & ~1023u;
    char* smal = smraw + (sb - sbr);

    if (tid < 32) TC_ALLOC(sb + 0, 512);
    if (tid == 0) { MBAR_INIT(sb + 8, 1); MBAR_INIT(sb + 16, 1); }
    __syncthreads();
    uint32_t tmem;
    asm volatile("ld.shared.b32 %0, [%1];" : "=r"(tmem) : "r"(sb + 0));

    // cp.async fill: 4 planes x 256 rows x 64B, SW64, 4 units/thread/plane
    #define FILLC(cc, stg) do {                                              \
        const __nv_bfloat16* _sp[4] = {Ahi + (cc) * KCH, Alo + (cc) * KCH,   \
                                       Bhi + (cc) * KCH, Blo + (cc) * KCH};  \
        _Pragma("unroll")                                                    \
        for (int p = 0; p < 4; p++) {                                        \
            _Pragma("unroll")                                                \
            for (int i = 0; i < 4; i++) {                                    \
                int idx = i * 256 + tid;                                     \
                int row = idx >> 2, u = idx & 3;                             \
                uint32_t bo = (uint32_t)(row * 64 + u * 16);                 \
                uint32_t sw = bo ^ ((bo >> 3) & 0x30);                       \
                cpa16((stg) + (uint32_t)p * PL64 + sw,                       \
                      _sp[p] + (size_t)row * EE + u * 8);                    \
            }                                                                \
        }                                                                    \
    } while (0)

    FILLC(0, sb + 1024);
    CP_COMMIT();

    int wp0 = 0, wp1 = 0;
    for (int c = 0; c < NC; c++) {
        uint32_t scur = sb + 1024 + (uint32_t)(c & 1) * TSTG;
        if (c + 1 < NC) {
            uint32_t snx = sb + 1024 + (uint32_t)((c + 1) & 1) * TSTG;
            if (c + 1 >= 2) {
                if (((c + 1) & 1) == 0) { MBAR_WAIT(sb + 8,  wp0); wp0 ^= 1; }
                else                    { MBAR_WAIT(sb + 16, wp1); wp1 ^= 1; }
            }
            FILLC(c + 1, snx);
            CP_COMMIT();
            CP_WAIT(1);
        } else {
            CP_WAIT(0);
        }
        __syncthreads();
        FENCE_ASYNC();
        if (tid < 32 && elect_one()) {
            #pragma unroll
            for (int rb = 0; rb < 2; rb++) {
                uint64_t dah = MK_DESC64(scur + rb * 8192);
                uint64_t dal = MK_DESC64(scur + PL64 + rb * 8192);
                #pragma unroll
                for (int cb = 0; cb < 2; cb++) {
                    uint64_t dbh = MK_DESC64(scur + 2 * PL64 + cb * 8192);
                    uint64_t dbl = MK_DESC64(scur + 3 * PL64 + cb * 8192);
                    uint32_t dt = tmem + rb * 256 + cb * 128;
                    #pragma unroll
                    for (int ks = 0; ks < 2; ks++) {
                        uint32_t en = (c > 0) || (ks > 0);
                        mma_f16_ss(dt, dah + ks * 2, dbh + ks * 2, GEMM_IDESC, en);
                        mma_f16_ss(dt, dah + ks * 2, dbl + ks * 2, GEMM_IDESC, 1);
                        mma_f16_ss(dt, dal + ks * 2, dbh + ks * 2, GEMM_IDESC, 1);
                    }
                }
            }
            TC_COMMIT(sb + 8 + 8 * (c & 1));
        }
    }
    MBAR_WAIT(sb + 8,  wp0);
    MBAR_WAIT(sb + 16, wp1);
    TC_FENCE_AFTER();

    // ---- staged epilogue: 4 passes (2 row-blocks x 2 col-blocks) ----
    int wg = tid >> 7, wiw = (tid >> 5) & 3, lane = tid & 31;
    float* sOut = (float*)(smal + 1024);   // 128 x 129 fp32 = 66048 B
    #pragma unroll
    for (int rb = 0; rb < 2; rb++) {
        #pragma unroll
        for (int cb2 = 0; cb2 < 2; cb2++) {
            uint32_t dreg[64];
            TC_LD_X32(dreg,      tmem + rb * 256 + cb2 * 128 + wg * 64);
            TC_LD_X32(dreg + 32, tmem + rb * 256 + cb2 * 128 + wg * 64 + 32);
            TC_WAIT_LD();
            __syncthreads();   // prior pass reads (or mainloop smem) done
            {
                int row = wiw * 32 + lane;
                #pragma unroll
                for (int j = 0; j < 64; j++)
                    sOut[row * 129 + wg * 64 + j] = __uint_as_float(dreg[j]);
            }
            __syncthreads();
            #pragma unroll
            for (int i = 0; i < 64; i++) {
                int idx = i * 256 + tid;
                int r = idx >> 7, cc = idx & 127;
                gemm_store(mz, m0 + rb * 128 + r, n0 + cb2 * 128 + cc,
                           sOut[r * 129 + cc], mode, bias, resid, op);
            }
        }
    }
    __syncthreads();
    if (tid < 32) { TC_RELINQ(); TC_DEALLOC(tmem, 512); }

#else  // ---------------- mma.sync fallback: 4x the proven 128x128 body ------
    extern __shared__ char smraw[];
    uint32_t sb = smem_u32(smraw);
    int wid = tid >> 5, lane = tid & 31;
    int wm = wid >> 1, wn = wid & 1;

    for (int sub = 0; sub < 4; sub++) {
        int sm0 = m0 + (sub >> 1) * 128;
        int sn0 = n0 + (sub & 1) * 128;
        const __nv_bfloat16* sAh = Ahi + (size_t)((sub >> 1) * 128) * EE;
        const __nv_bfloat16* sAl = Alo + (size_t)((sub >> 1) * 128) * EE;
        const __nv_bfloat16* sBh = Bhi + (size_t)((sub & 1) * 128) * EE;
        const __nv_bfloat16* sBl = Blo + (size_t)((sub & 1) * 128) * EE;

        float acc[2][8][4];
        #pragma unroll
        for (int a = 0; a < 2; a++)
            #pragma unroll
            for (int b = 0; b < 8; b++)
                #pragma unroll
                for (int c = 0; c < 4; c++) acc[a][b][c] = 0.f;

        #define LOAD_CHUNK(cc, stg) do {                                     \
            const __nv_bfloat16* _s[4] = {sAh + (cc) * KCH, sAl + (cc) * KCH,\
                                          sBh + (cc) * KCH, sBl + (cc) * KCH};\
            _Pragma("unroll")                                                \
            for (int p = 0; p < 4; p++) {                                    \
                _Pragma("unroll")                                            \
                for (int i = 0; i < 2; i++) {                                \
                    int idx = i * 256 + tid;                                 \
                    int r = idx >> 2, cg = (idx & 3) * 8;                    \
                    cpa16((stg) + p * PLN2 + (r * GLD2 + cg) * 2,            \
                          _s[p] + (size_t)r * EE + cg);                      \
                }                                                            \
            }                                                                \
        } while (0)

        __syncthreads();
        LOAD_CHUNK(0, sb);
        CP_COMMIT();

        for (int c = 0; c < NC; c++) {
            if (c + 1 < NC) {
                LOAD_CHUNK(c + 1, sb + (uint32_t)((c + 1) & 1) * STG2);
                CP_COMMIT();
                CP_WAIT(1);
            } else {
                CP_WAIT(0);
            }
            __syncthreads();
            uint32_t sk = sb + (uint32_t)(c & 1) * STG2;
            #pragma unroll
            for (int ks = 0; ks < 2; ks++) {
                uint32_t ah[2][4], al[2][4];
                #pragma unroll
                for (int mt = 0; mt < 2; mt++) {
                    uint32_t ad = sk +
                        ((wm * 32 + mt * 16 + (lane & 15)) * GLD2 + ks * 16 + ((lane >> 4) * 8)) * 2;
                    ldsm4(ah[mt], ad);
                    ldsm4(al[mt], ad + PLN2);
                }
                #pragma unroll
                for (int g = 0; g < 4; g++) {
                    uint32_t r4h[4], r4l[4];
                    uint32_t bd = sk + 2 * PLN2 +
                        ((wn * 64 + g * 16 + (lane & 15)) * GLD2 + ks * 16 + ((lane >> 4) * 8)) * 2;
                    ldsm4(r4h, bd);
                    ldsm4(r4l, bd + PLN2);
                    uint32_t bh0[2] = {r4h[0], r4h[2]}, bh1[2] = {r4h[1], r4h[3]};
                    uint32_t bl0[2] = {r4l[0], r4l[2]}, bl1[2] = {r4l[1], r4l[3]};
                    #pragma unroll
                    for (int mt = 0; mt < 2; mt++) {
                        mma16816(acc[mt][g*2],   ah[mt], bh0);
                        mma16816(acc[mt][g*2],   ah[mt], bl0);
                        mma16816(acc[mt][g*2],   al[mt], bh0);
                        mma16816(acc[mt][g*2+1], ah[mt], bh1);
                        mma16816(acc[mt][g*2+1], ah[mt], bl1);
                        mma16816(acc[mt][g*2+1], al[mt], bh1);
                    }
                }
            }
            __syncthreads();
        }

        #pragma unroll
        for (int mt = 0; mt < 2; mt++) {
            int r0 = sm0 + wm * 32 + mt * 16 + (lane >> 2);
            #pragma unroll
            for (int j = 0; j < 8; j++) {
                int c0 = sn0 + wn * 64 + j * 8 + (lane & 3) * 2;
                #pragma unroll
                for (int e = 0; e < 4; e++)
                    gemm_store(mz, r0 + (e >> 1) * 8, c0 + (e & 1), acc[mt][j][e],
                               mode, bias, resid, op);
            }
        }
    }
#endif
}

// ---------------- fused FA2 flash attention (unchanged from R11) -------------
#define ALD 72
#define QPLN (128 * ALD * 2)
#define KPLN (64 * ALD * 2)
#define STG  (3 * KPLN)              // Khi, Klo, V16
#define ATT_SMEM (2*QPLN + 2*STG)    // 92160

__device__ __forceinline__ void load_kv_stage(
        uint32_t stg, int kt, int tid,
        const __nv_bfloat16* khig, const __nv_bfloat16* klog,
        const __half* v16g) {
    #pragma unroll
    for (int i = 0; i < 2; i++) {
        int idx = i * 256 + tid;
        int r = idx >> 3, c8 = (idx & 7) * 8;
        size_t gofs = (size_t)(kt * 64 + r) * DD + c8;
        uint32_t so = (uint32_t)(r * ALD + c8) * 2;
        cpa16(stg + so,            khig + gofs);
        cpa16(stg + KPLN + so,     klog + gofs);
        cpa16(stg + 2 * KPLN + so, v16g + gofs);
    }
}

__global__ __launch_bounds__(256, 2) void attn_fused() {
    extern __shared__ char smraw[];
    __nv_bfloat16* sQh = (__nv_bfloat16*)smraw;
    __nv_bfloat16* sQl = sQh + 128 * ALD;
    uint32_t sb = smem_u32(smraw);

    int z = blockIdx.z, mz = z >> 1, b = z & 1;
    int h = blockIdx.y;
    int q0 = blockIdx.x * 128;
    int tid = threadIdx.x, wid = tid >> 5, lane = tid & 31;
    int rb = wid * 16;
    int tg = lane >> 2, tig = lane & 3;

    size_t hb = (size_t)mz * QSZ + (size_t)(b * HH + h) * NN * DD;
    const __nv_bfloat16* khig = g_khi + hb;
    const __nv_bfloat16* klog = g_klo + hb;
    const __half*        v16g = g_v16 + hb;

    #pragma unroll
    for (int i = 0; i < 4; i++) {
        int idx = i * 256 + tid;
        int r = idx >> 3, c8 = (idx & 7) * 8;
        size_t gq = hb + (size_t)(q0 + r) * DD + c8;
        *(uint4*)(sQh + r * ALD + c8) = *(const uint4*)(g_qhi + gq);
        *(uint4*)(sQl + r * ALD + c8) = *(const uint4*)(g_qlo + gq);
    }
    load_kv_stage(sb + 2 * QPLN, 0, tid, khig, klog, v16g);
    CP_COMMIT();
    __syncthreads();

    uint32_t qh[4][4];
    #pragma unroll
    for (int ks = 0; ks < 4; ks++)
        ldsm4(qh[ks], sb + ((rb + (lane & 15)) * ALD + ks * 16 + ((lane >> 4) * 8)) * 2);

    float o[8][4];
    #pragma unroll
    for (int g = 0; g < 8; g++)
        #pragma unroll
        for (int e = 0; e < 4; e++) o[g][e] = 0.f;
    float m0 = -1e30f, m1 = -1e30f, l0 = 0.f, l1 = 0.f;

    const int NT = NN / 64;
    for (int kt = 0; kt < NT; kt++) {
        uint32_t sk = sb + 2 * QPLN + (uint32_t)(kt & 1) * STG;
        if (kt + 1 < NT) {
            load_kv_stage(sb + 2 * QPLN + (uint32_t)((kt + 1) & 1) * STG,
                          kt + 1, tid, khig, klog, v16g);
            CP_COMMIT();
            CP_WAIT(1);
        } else {
            CP_WAIT(0);
        }
        __syncthreads();

        float s[8][4];
        #pragma unroll
        for (int g = 0; g < 8; g++)
            #pragma unroll
            for (int e = 0; e < 4; e++) s[g][e] = 0.f;
        #pragma unroll
        for (int ks = 0; ks < 4; ks++) {
            uint32_t ql4[4];
            ldsm4(ql4, sb + QPLN + ((rb + (lane & 15)) * ALD + ks * 16 + ((lane >> 4) * 8)) * 2);
            #pragma unroll
            for (int nb = 0; nb < 4; nb++) {
                uint32_t r4h[4], r4l[4];
                uint32_t bd = sk + ((nb * 16 + (lane & 15)) * ALD + ks * 16 + ((lane >> 4) * 8)) * 2;
                ldsm4(r4h, bd);
                ldsm4(r4l, bd + KPLN);
                uint32_t bh0[2] = {r4h[0], r4h[2]}, bh1[2] = {r4h[1], r4h[3]};
                uint32_t bl0[2] = {r4l[0], r4l[2]}, bl1[2] = {r4l[1], r4l[3]};
                mma16816(s[nb*2],   qh[ks], bh0);
                mma16816(s[nb*2],   qh[ks], bl0);
                mma16816(s[nb*2],   ql4,    bh0);
                mma16816(s[nb*2+1], qh[ks], bh1);
                mma16816(s[nb*2+1], qh[ks], bl1);
                mma16816(s[nb*2+1], ql4,    bh1);
            }
        }

        float mx0 = -1e30f, mx1 = -1e30f;
        #pragma unroll
        for (int g = 0; g < 8; g++) {
            mx0 = fmaxf(mx0, fmaxf(s[g][0], s[g][1]));
            mx1 = fmaxf(mx1, fmaxf(s[g][2], s[g][3]));
        }
        mx0 = fmaxf(mx0, __shfl_xor_sync(0xffffffffu, mx0, 1));
        mx0 = fmaxf(mx0, __shfl_xor_sync(0xffffffffu, mx0, 2));
        mx1 = fmaxf(mx1, __shfl_xor_sync(0xffffffffu, mx1, 1));
        mx1 = fmaxf(mx1, __shfl_xor_sync(0xffffffffu, mx1, 2));
        float nm0 = fmaxf(m0, mx0), nm1 = fmaxf(m1, mx1);
        float a0 = ex2f(m0 - nm0), a1 = ex2f(m1 - nm1);
        m0 = nm0; m1 = nm1;

        uint32_t ph01[8], ph23[8];
        float sum0 = 0.f, sum1 = 0.f;
        #pragma unroll
        for (int g = 0; g < 8; g++) {
            float e0 = ex2f(s[g][0] - nm0), e1 = ex2f(s[g][1] - nm0);
            float e2 = ex2f(s[g][2] - nm1), e3 = ex2f(s[g][3] - nm1);
            sum0 += e0 + e1;  sum1 += e2 + e3;
            ph01[g] = cvth2(e1, e0);
            ph23[g] = cvth2(e3, e2);
        }
        sum0 += __shfl_xor_sync(0xffffffffu, sum0, 1);
        sum0 += __shfl_xor_sync(0xffffffffu, sum0, 2);
        sum1 += __shfl_xor_sync(0xffffffffu, sum1, 1);
        sum1 += __shfl_xor_sync(0xffffffffu, sum1, 2);
        l0 = l0 * a0 + sum0;
        l1 = l1 * a1 + sum1;
        #pragma unroll
        for (int g = 0; g < 8; g++) {
            o[g][0] *= a0; o[g][1] *= a0;
            o[g][2] *= a1; o[g][3] *= a1;
        }

        uint32_t sv = sk + 2 * KPLN;
        #pragma unroll
        for (int kg = 0; kg < 4; kg++) {
            uint32_t aph[4] = {ph01[2*kg], ph23[2*kg], ph01[2*kg+1], ph23[2*kg+1]};
            #pragma unroll
            for (int db = 0; db < 4; db++) {
                uint32_t r4[4];
                ldsm4t(r4, sv + ((kg * 16 + (lane & 15)) * ALD + db * 16 + ((lane >> 4) * 8)) * 2);
                uint32_t bh0[2] = {r4[0], r4[1]}, bh1[2] = {r4[2], r4[3]};
                mma16816h(o[db*2],   aph, bh0);
                mma16816h(o[db*2+1], aph, bh1);
            }
        }
        __syncthreads();
    }

    float inv0 = 1.0f / l0, inv1 = 1.0f / l1;
    int rr0 = q0 + rb + tg;
    size_t mofs = (size_t)mz * MM * EE;
    #pragma unroll
    for (int g = 0; g < 8; g++) {
        int dd = g * 8 + tig * 2;
        size_t o0 = mofs + ((size_t)b * NN + rr0) * EE + h * DD + dd;
        split_st(g_att_hi, g_att_lo, o0,     o[g][0] * inv0);
        split_st(g_att_hi, g_att_lo, o0 + 1, o[g][1] * inv0);
        size_t o8 = o0 + (size_t)8 * EE;
        split_st(g_att_hi, g_att_lo, o8,     o[g][2] * inv1);
        split_st(g_att_hi, g_att_lo, o8 + 1, o[g][3] * inv1);
    }
}

// ---------------- launch -----------------------------------------------------
extern "C" void kernel_launch(void* const* d_in, const int* in_sizes, int n_in,
                              void* d_out, int out_size) {
    const float* in[14];
    for (int i = 0; i < 14; i++) in[i] = (const float*)d_in[i];
    float* out = (float*)d_out;

    cudaFuncSetAttribute(gemm_fused,
                         cudaFuncAttributeMaxDynamicSharedMemorySize, GEMM_SMEM_HOST);
    cudaFuncSetAttribute(attn_fused,
                         cudaFuncAttributeMaxDynamicSharedMemorySize, ATT_SMEM);

    ln_fused<<<2 * MM, 256>>>(in[0], in[1], in[2], in[3], in[8], in[9]);
    {
        size_t ntot = 2 * NQKV + 2 * NPROJ;
        split_fused<<<(unsigned)((ntot + 255) / 256), 256>>>(in[4], in[6], in[10], in[12]);
    }
    gemm_fused<<<dim3(E3 / 256, MM / 256, 2), 256, GEMM_SMEM_HOST>>>(
        in[5], in[11], nullptr, nullptr, nullptr, 0);
    attn_fused<<<dim3(NN / 128, HH, 2 * BB), 256, ATT_SMEM>>>();
    gemm_fused<<<dim3(EE / 256, MM / 256, 2), 256, GEMM_SMEM_HOST>>>(
        in[7], in[13], in[0], in[1], out, 1);
}

// round 16
// speedup vs baseline: 1.1279x; 1.1279x over previous
#include <cuda_runtime.h>
#include <cuda_bf16.h>
#include <cuda_fp16.h>
#include <cstdint>

// Problem constants
#define BB 2
#define NN 2048
#define EE 768
#define HH 12
#define DD 64
#define E3 (3*EE)
#define MM (BB*NN)   // 4096 rows per modality

// 8 * log2(e): folds softmax exp->exp2 into the Q scale
#define QSCALE 11.541560327111707f

#define NQKV ((size_t)E3 * EE)
#define NPROJ ((size_t)EE * EE)
#define QSZ ((size_t)BB * HH * NN * DD)

// tcgen05 is architecture-SPECIFIC (sm_103a). Non-specific pass -> mma.sync.
#if defined(__CUDA_ARCH_FEAT_SM103_ALL) || defined(__CUDA_ARCH_FEAT_SM100_ALL) || \
    defined(__CUDA_ARCH_FEAT_SM101_ALL) || \
    (defined(__CUDA_ARCH_SPECIFIC__) && (__CUDA_ARCH_SPECIFIC__ >= 1000)) || \
    (defined(__CUDA_ARCH_FAMILY_SPECIFIC__) && (__CUDA_ARCH_FAMILY_SPECIFIC__ >= 1000))
#define HAS_TCGEN05 1
#else
#define HAS_TCGEN05 0
#endif

// ------------------------------ helpers ------------------------------------
__device__ __forceinline__ uint32_t smem_u32(const void* p) {
    uint32_t a;
    asm("{ .reg .u64 t; cvta.to.shared.u64 t, %1; cvt.u32.u64 %0, t; }"
        : "=r"(a) : "l"(p));
    return a;
}
__device__ __forceinline__ void ldsm4(uint32_t* r, uint32_t addr) {
    asm volatile("ldmatrix.sync.aligned.m8n8.x4.shared.b16 {%0,%1,%2,%3}, [%4];"
        : "=r"(r[0]), "=r"(r[1]), "=r"(r[2]), "=r"(r[3]) : "r"(addr));
}
__device__ __forceinline__ void ldsm4t(uint32_t* r, uint32_t addr) {
    asm volatile("ldmatrix.sync.aligned.m8n8.x4.trans.shared.b16 {%0,%1,%2,%3}, [%4];"
        : "=r"(r[0]), "=r"(r[1]), "=r"(r[2]), "=r"(r[3]) : "r"(addr));
}
__device__ __forceinline__ void mma16816(float* c, const uint32_t* a, const uint32_t* b) {
    asm volatile("mma.sync.aligned.m16n8k16.row.col.f32.bf16.bf16.f32 "
        "{%0,%1,%2,%3}, {%4,%5,%6,%7}, {%8,%9}, {%0,%1,%2,%3};"
        : "+f"(c[0]), "+f"(c[1]), "+f"(c[2]), "+f"(c[3])
        : "r"(a[0]), "r"(a[1]), "r"(a[2]), "r"(a[3]), "r"(b[0]), "r"(b[1]));
}
__device__ __forceinline__ void mma16816h(float* c, const uint32_t* a, const uint32_t* b) {
    asm volatile("mma.sync.aligned.m16n8k16.row.col.f32.f16.f16.f32 "
        "{%0,%1,%2,%3}, {%4,%5,%6,%7}, {%8,%9}, {%0,%1,%2,%3};"
        : "+f"(c[0]), "+f"(c[1]), "+f"(c[2]), "+f"(c[3])
        : "r"(a[0]), "r"(a[1]), "r"(a[2]), "r"(a[3]), "r"(b[0]), "r"(b[1]));
}
__device__ __forceinline__ float ex2f(float x) {
    float y; asm("ex2.approx.f32 %0, %1;" : "=f"(y) : "f"(x)); return y;
}
__device__ __forceinline__ uint32_t cvth2(float hi, float lo) {
    uint32_t r; asm("cvt.rn.f16x2.f32 %0, %1, %2;" : "=r"(r) : "f"(hi), "f"(lo));
    return r;
}
__device__ __forceinline__ void cpa16(uint32_t dst, const void* src) {
    asm volatile("cp.async.cg.shared.global [%0], [%1], 16;" :: "r"(dst), "l"(src));
}
#define CP_COMMIT() asm volatile("cp.async.commit_group;" ::: "memory")
#define CP_WAIT(n)  asm volatile("cp.async.wait_group %0;" :: "n"(n) : "memory")

__device__ __forceinline__ void split_st(__nv_bfloat16* hi, __nv_bfloat16* lo,
                                         size_t idx, float v) {
    __nv_bfloat16 h = __float2bfloat16(v);
    hi[idx] = h;
    lo[idx] = __float2bfloat16(v - __bfloat162float(h));
}

#if HAS_TCGEN05
__device__ __forceinline__ uint32_t elect_one() {
    uint32_t pred;
    asm volatile("{\n\t.reg .pred p;\n\telect.sync _|p, 0xFFFFFFFF;\n\t"
                 "selp.b32 %0, 1, 0, p;\n\t}" : "=r"(pred));
    return pred;
}
#define MBAR_INIT(a, c) \
    asm volatile("mbarrier.init.shared.b64 [%0], %1;" :: "r"(a), "r"(c) : "memory")
#define MBAR_WAIT(a, ph) do {                                                   \
    uint32_t _m = (a), _p = (ph), _d;                                           \
    asm volatile("{\n\t.reg .pred p;\n\t"                                       \
        "mbarrier.try_wait.parity.acquire.cta.shared::cta.b64 p, [%1], %2;\n\t" \
        "selp.b32 %0, 1, 0, p;\n\t}" : "=r"(_d) : "r"(_m), "r"(_p) : "memory"); \
    if (!_d) {                                                                  \
        asm volatile("{\n\t.reg .pred P1;\n\tWL_%=: \n\t"                       \
            "mbarrier.try_wait.parity.acquire.cta.shared::cta.b64 P1, [%0], %1, 0x989680;\n\t" \
            "@P1 bra.uni WD_%=;\n\tbra.uni WL_%=;\n\tWD_%=:\n\t}"               \
            :: "r"(_m), "r"(_p) : "memory");                                    \
    }                                                                           \
} while (0)
#define TC_ALLOC(sa, n) \
    asm volatile("tcgen05.alloc.cta_group::1.sync.aligned.shared::cta.b32 [%0], %1;" \
                 :: "r"(sa), "r"(n) : "memory")
#define TC_DEALLOC(t, n) \
    asm volatile("tcgen05.dealloc.cta_group::1.sync.aligned.b32 %0, %1;" :: "r"(t), "r"(n))
#define TC_RELINQ() \
    asm volatile("tcgen05.relinquish_alloc_permit.cta_group::1.sync.aligned;")
#define TC_COMMIT(mb) \
    asm volatile("tcgen05.commit.cta_group::1.mbarrier::arrive::one.shared::cluster.b64 [%0];" \
                 :: "r"(mb) : "memory")
#define TC_FENCE_AFTER() asm volatile("tcgen05.fence::after_thread_sync;" ::: "memory")
#define TC_WAIT_LD() asm volatile("tcgen05.wait::ld.sync.aligned;" ::: "memory")
#define FENCE_ASYNC() asm volatile("fence.proxy.async.shared::cta;" ::: "memory")
#define TC_LD_X32(r, ta) \
    asm volatile("tcgen05.ld.sync.aligned.32x32b.x32.b32 " \
        "{%0, %1, %2, %3, %4, %5, %6, %7, %8, %9, %10, %11, %12, %13, %14, %15, " \
        " %16, %17, %18, %19, %20, %21, %22, %23, %24, %25, %26, %27, %28, %29, %30, %31}, [%32];" \
        : "=r"((r)[0]),  "=r"((r)[1]),  "=r"((r)[2]),  "=r"((r)[3]),  \
          "=r"((r)[4]),  "=r"((r)[5]),  "=r"((r)[6]),  "=r"((r)[7]),  \
          "=r"((r)[8]),  "=r"((r)[9]),  "=r"((r)[10]), "=r"((r)[11]), \
          "=r"((r)[12]), "=r"((r)[13]), "=r"((r)[14]), "=r"((r)[15]), \
          "=r"((r)[16]), "=r"((r)[17]), "=r"((r)[18]), "=r"((r)[19]), \
          "=r"((r)[20]), "=r"((r)[21]), "=r"((r)[22]), "=r"((r)[23]), \
          "=r"((r)[24]), "=r"((r)[25]), "=r"((r)[26]), "=r"((r)[27]), \
          "=r"((r)[28]), "=r"((r)[29]), "=r"((r)[30]), "=r"((r)[31]) \
        : "r"(ta))

// SW128 smem descriptor: layout=SW128(2), version=1, SBO=64, LBO=1 (K-major)
static constexpr uint64_t DESC_BASE =
    (uint64_t(2) << 61) | (uint64_t(1) << 46) | (uint64_t(64) << 32) | (uint64_t(1) << 16);
#define MK_DESC(a) (DESC_BASE | ((uint64_t)((a) >> 4) & 0x3FFF))

// cg1 bf16 SS MMA idesc: F32 acc | BF16 a | BF16 b | N=128 | M=128
static constexpr uint32_t GEMM_IDESC =
    (1u << 4) | (1u << 7) | (1u << 10) | ((128u / 8) << 17) | ((128u / 16) << 24);

__device__ __forceinline__ void mma_f16_ss(uint32_t d, uint64_t a, uint64_t b,
                                           uint32_t idesc, uint32_t en) {
    asm volatile("{\n\t.reg .pred p;\n\tsetp.ne.u32 p, %4, 0;\n\t"
        "tcgen05.mma.cta_group::1.kind::f16 [%0], %1, %2, %3, {%5,%5,%5,%5}, p;\n\t}"
        :: "r"(d), "l"(a), "l"(b), "r"(idesc), "r"(en), "r"(0u) : "memory");
}
#endif

// ---------------- scratch (device globals; DEVICE-SIDE refs only!) ---------
__device__ __align__(256) __nv_bfloat16 g_xn_hi[2*MM*EE],  g_xn_lo[2*MM*EE];
__device__ __align__(256) __nv_bfloat16 g_att_hi[2*MM*EE], g_att_lo[2*MM*EE];
__device__ __align__(256) __nv_bfloat16 g_w_hi[2*(E3+EE)*EE], g_w_lo[2*(E3+EE)*EE];
__device__ __align__(256) __nv_bfloat16 g_qhi[2*BB*HH*NN*DD], g_qlo[2*BB*HH*NN*DD];
__device__ __align__(256) __nv_bfloat16 g_khi[2*BB*HH*NN*DD], g_klo[2*BB*HH*NN*DD];
__device__ __align__(256) __half        g_v16[2*BB*HH*NN*DD];   // V: single fp16 plane

// ---------------- merged prologue: LN (both modalities) + weight split -------
// blocks [0, 2*MM): LayerNorm rows. blocks [2*MM, ...): vectorized weight split.
#define SPLIT_ELEMS (2*NQKV + 2*NPROJ)                 // 4718592 (div by 4)
#define SPLIT_BLOCKS ((unsigned)(SPLIT_ELEMS / 4 / 256))  // 4608
__global__ __launch_bounds__(256) void pre_fused(
        const float* __restrict__ x0, const float* __restrict__ x1,
        const float* __restrict__ g0, const float* __restrict__ b0,
        const float* __restrict__ g1, const float* __restrict__ b1,
        const float* __restrict__ wq0, const float* __restrict__ wp0,
        const float* __restrict__ wq1, const float* __restrict__ wp1) {
    int bid = blockIdx.x;
    int t = threadIdx.x;
    if (bid < 2 * MM) {
        // ---- LayerNorm ----
        int grow = bid;
        int mz = grow >> 12;
        const float* x = mz ? x1 : x0;
        const float* g = mz ? g1 : g0;
        const float* bta = mz ? b1 : b0;
        const float* xr = x + (size_t)(grow & (MM - 1)) * EE;
        float v0 = xr[t], v1 = xr[t + 256], v2 = xr[t + 512];
        float s  = v0 + v1 + v2;
        float sq = v0*v0 + v1*v1 + v2*v2;
        __shared__ float rs[8], rq[8];
        #pragma unroll
        for (int o = 16; o; o >>= 1) {
            s  += __shfl_xor_sync(0xffffffffu, s,  o);
            sq += __shfl_xor_sync(0xffffffffu, sq, o);
        }
        if ((t & 31) == 0) { rs[t >> 5] = s; rq[t >> 5] = sq; }
        __syncthreads();
        float S = 0.f, Q = 0.f;
        #pragma unroll
        for (int i = 0; i < 8; i++) { S += rs[i]; Q += rq[i]; }
        float mu  = S * (1.0f / EE);
        float var = Q * (1.0f / EE) - mu * mu;
        float inv = rsqrtf(var + 1e-5f);
        #pragma unroll
        for (int p = 0; p < 3; p++) {
            int c = t + p * 256;
            float v = (p == 0 ? v0 : p == 1 ? v1 : v2);
            float y = (v - mu) * inv * g[c] + bta[c];
            split_st(g_xn_hi, g_xn_lo, (size_t)grow * EE + c, y);
        }
    } else {
        // ---- vectorized weight split: 4 fp32 -> 4 hi + 4 lo bf16 ----
        size_t i = ((size_t)(bid - 2 * MM) * 256 + t) * 4;
        if (i >= SPLIT_ELEMS) return;
        const float* src;
        size_t ofs;
        if (i < NQKV)                { src = wq0; ofs = i; }
        else if (i < 2 * NQKV)       { src = wq1; ofs = i - NQKV; }
        else if (i < 2 * NQKV + NPROJ) { src = wp0; ofs = i - 2 * NQKV; }
        else                         { src = wp1; ofs = i - 2 * NQKV - NPROJ; }
        float4 v = *(const float4*)(src + ofs);
        __nv_bfloat16 h0 = __float2bfloat16(v.x), h1 = __float2bfloat16(v.y);
        __nv_bfloat16 h2 = __float2bfloat16(v.z), h3 = __float2bfloat16(v.w);
        __nv_bfloat162* hp = (__nv_bfloat162*)(g_w_hi + i);
        hp[0] = __nv_bfloat162(h0, h1);
        hp[1] = __nv_bfloat162(h2, h3);
        __nv_bfloat162* lp = (__nv_bfloat162*)(g_w_lo + i);
        lp[0] = __nv_bfloat162(__float2bfloat16(v.x - __bfloat162float(h0)),
                               __float2bfloat16(v.y - __bfloat162float(h1)));
        lp[1] = __nv_bfloat162(__float2bfloat16(v.z - __bfloat162float(h2)),
                               __float2bfloat16(v.w - __bfloat162float(h3)));
    }
}

// ---------------- GEMM epilogue store ----------------------------------------
__device__ __forceinline__ void gemm_store(int mz, int gr, int gc, float accv,
        int mode, const float* __restrict__ bias,
        const float* __restrict__ resid, float* __restrict__ outp) {
    float val = accv + bias[gc];
    if (mode == 0) {
        int bI = gr >> 11, nI = gr & (NN - 1);
        int t3 = gc / 3;
        int s3 = gc - 3 * t3;
        int dd = t3 & 63;
        int hh = gc / 192;
        size_t idx = (size_t)mz * QSZ + ((size_t)(bI * HH + hh) * NN + nI) * DD + dd;
        if (s3 == 0)      split_st(g_qhi, g_qlo, idx, val * QSCALE);
        else if (s3 == 1) split_st(g_khi, g_klo, idx, val);
        else              g_v16[idx] = __float2half(val);
    } else {
        outp[(size_t)gr * EE + gc] = resid[(size_t)gr * EE + gc] + val;
    }
}

// ---------------- fused split-bf16 GEMM (R13: best measured config) ----------
#define RTILE 16384
#define TSTG  (4*RTILE)
#define GEMM_SMEM_HOST (2048 + 2*TSTG)  // 133120 B

#define KCH 32
#define NC (EE/KCH)
#define GLD2 40
#define PLN2 (128*GLD2*2)
#define STG2 (4*PLN2)

__global__ __launch_bounds__(256) void gemm_fused(
        const float* __restrict__ bias0, const float* __restrict__ bias1,
        const float* __restrict__ resid0, const float* __restrict__ resid1,
        float* __restrict__ outp, int mode) {
    int tid = threadIdx.x;
    int mz = blockIdx.z;
    int m0 = blockIdx.y * 128, n0 = blockIdx.x * 128;

    const __nv_bfloat16* Ahi = (mode == 0 ? g_xn_hi : g_att_hi)
                               + (size_t)mz * MM * EE + (size_t)m0 * EE;
    const __nv_bfloat16* Alo = (mode == 0 ? g_xn_lo : g_att_lo)
                               + (size_t)mz * MM * EE + (size_t)m0 * EE;
    size_t bofs = (mode == 0) ? (size_t)mz * NQKV : 2 * NQKV + (size_t)mz * NPROJ;
    const __nv_bfloat16* Bhi = g_w_hi + bofs + (size_t)n0 * EE;
    const __nv_bfloat16* Blo = g_w_lo + bofs + (size_t)n0 * EE;
    const float* bias  = mz ? bias1 : bias0;
    const float* resid = mz ? resid1 : resid0;
    float* op = outp + (size_t)mz * MM * EE;

#if HAS_TCGEN05
    extern __shared__ char smraw[];
    uint32_t sbr = smem_u32(smraw);
    uint32_t sb  = (sbr + 1023u) & ~1023u;
    char* smal = smraw + (sb - sbr);

    if (tid < 32) TC_ALLOC(sb + 0, 128);
    if (tid == 0) { MBAR_INIT(sb + 8, 1); MBAR_INIT(sb + 16, 1); }
    __syncthreads();
    uint32_t tmem;
    asm volatile("ld.shared.b32 %0, [%1];" : "=r"(tmem) : "r"(sb + 0));

    #define FILLC(cc, stg) do {                                              \
        const __nv_bfloat16* _sp[4] = {Ahi + (cc) * 64, Alo + (cc) * 64,     \
                                       Bhi + (cc) * 64, Blo + (cc) * 64};    \
        _Pragma("unroll")                                                    \
        for (int p = 0; p < 4; p++) {                                        \
            _Pragma("unroll")                                                \
            for (int i = 0; i < 4; i++) {                                    \
                int idx = i * 256 + tid;                                     \
                int row = idx >> 3, c16 = idx & 7;                           \
                uint32_t bo = (uint32_t)(row * 128 + c16 * 16);              \
                uint32_t sw = bo ^ ((bo >> 3) & 0x70);                       \
                cpa16((stg) + (uint32_t)p * RTILE + sw,                      \
                      _sp[p] + (size_t)row * EE + c16 * 8);                  \
            }                                                                \
        }                                                                    \
    } while (0)

    FILLC(0, sb + 1024);
    CP_COMMIT();

    int wp0 = 0, wp1 = 0;
    for (int c = 0; c < 12; c++) {
        uint32_t scur = sb + 1024 + (uint32_t)(c & 1) * TSTG;
        if (c + 1 < 12) {
            uint32_t snx = sb + 1024 + (uint32_t)((c + 1) & 1) * TSTG;
            if (c + 1 >= 2) {
                if (((c + 1) & 1) == 0) { MBAR_WAIT(sb + 8,  wp0); wp0 ^= 1; }
                else                    { MBAR_WAIT(sb + 16, wp1); wp1 ^= 1; }
            }
            FILLC(c + 1, snx);
            CP_COMMIT();
            CP_WAIT(1);
        } else {
            CP_WAIT(0);
        }
        __syncthreads();
        FENCE_ASYNC();
        if (tid < 32 && elect_one()) {
            uint64_t dah = MK_DESC(scur);
            uint64_t dal = MK_DESC(scur + RTILE);
            uint64_t dbh = MK_DESC(scur + 2 * RTILE);
            uint64_t dbl = MK_DESC(scur + 3 * RTILE);
            #pragma unroll
            for (int ks = 0; ks < 4; ks++) {
                mma_f16_ss(tmem, dah + ks * 2, dbh + ks * 2, GEMM_IDESC, (c > 0) || (ks > 0));
                mma_f16_ss(tmem, dah + ks * 2, dbl + ks * 2, GEMM_IDESC, 1);
                mma_f16_ss(tmem, dal + ks * 2, dbh + ks * 2, GEMM_IDESC, 1);
            }
            TC_COMMIT(sb + 8 + 8 * (c & 1));
        }
    }
    MBAR_WAIT(sb + 8,  wp0);
    MBAR_WAIT(sb + 16, wp1);
    TC_FENCE_AFTER();

    // ---- staged epilogue: TMEM -> smem (conflict-free) -> coalesced gmem ----
    int wg = tid >> 7, wiw = (tid >> 5) & 3, lane = tid & 31;
    uint32_t dreg[64];
    TC_LD_X32(dreg,      tmem + wg * 64);
    TC_LD_X32(dreg + 32, tmem + wg * 64 + 32);
    TC_WAIT_LD();
    __syncthreads();                       // mainloop smem fully consumed

    float* sOut = (float*)(smal + 1024);   // 128 x 129 fp32 = 66048 B
    {
        int row = wiw * 32 + lane;
        #pragma unroll
        for (int j = 0; j < 64; j++)
            sOut[row * 129 + wg * 64 + j] = __uint_as_float(dreg[j]);
    }
    __syncthreads();
    #pragma unroll
    for (int i = 0; i < 64; i++) {
        int idx = i * 256 + tid;
        int r = idx >> 7, cc = idx & 127;
        gemm_store(mz, m0 + r, n0 + cc, sOut[r * 129 + cc], mode, bias, resid, op);
    }
    __syncthreads();
    if (tid < 32) { TC_RELINQ(); TC_DEALLOC(tmem, 128); }

#else  // ---------------- mma.sync fallback (R11) ----------------------------
    extern __shared__ char smraw[];
    uint32_t sb = smem_u32(smraw);
    int wid = tid >> 5, lane = tid & 31;
    int wm = wid >> 1, wn = wid & 1;

    float acc[2][8][4];
    #pragma unroll
    for (int a = 0; a < 2; a++)
        #pragma unroll
        for (int b = 0; b < 8; b++)
            #pragma unroll
            for (int c = 0; c < 4; c++) acc[a][b][c] = 0.f;

    #define LOAD_CHUNK(cc, stg) do {                                         \
        const __nv_bfloat16* _s[4] = {Ahi + (cc) * KCH, Alo + (cc) * KCH,    \
                                      Bhi + (cc) * KCH, Blo + (cc) * KCH};   \
        _Pragma("unroll")                                                    \
        for (int p = 0; p < 4; p++) {                                        \
            _Pragma("unroll")                                                \
            for (int i = 0; i < 2; i++) {                                    \
                int idx = i * 256 + tid;                                     \
                int r = idx >> 2, cg = (idx & 3) * 8;                        \
                cpa16((stg) + p * PLN2 + (r * GLD2 + cg) * 2,                \
                      _s[p] + (size_t)r * EE + cg);                          \
            }                                                                \
        }                                                                    \
    } while (0)

    LOAD_CHUNK(0, sb);
    CP_COMMIT();

    for (int c = 0; c < NC; c++) {
        if (c + 1 < NC) {
            LOAD_CHUNK(c + 1, sb + (uint32_t)((c + 1) & 1) * STG2);
            CP_COMMIT();
            CP_WAIT(1);
        } else {
            CP_WAIT(0);
        }
        __syncthreads();
        uint32_t sk = sb + (uint32_t)(c & 1) * STG2;
        #pragma unroll
        for (int ks = 0; ks < 2; ks++) {
            uint32_t ah[2][4], al[2][4];
            #pragma unroll
            for (int mt = 0; mt < 2; mt++) {
                uint32_t ad = sk +
                    ((wm * 32 + mt * 16 + (lane & 15)) * GLD2 + ks * 16 + ((lane >> 4) * 8)) * 2;
                ldsm4(ah[mt], ad);
                ldsm4(al[mt], ad + PLN2);
            }
            #pragma unroll
            for (int g = 0; g < 4; g++) {
                uint32_t r4h[4], r4l[4];
                uint32_t bd = sk + 2 * PLN2 +
                    ((wn * 64 + g * 16 + (lane & 15)) * GLD2 + ks * 16 + ((lane >> 4) * 8)) * 2;
                ldsm4(r4h, bd);
                ldsm4(r4l, bd + PLN2);
                uint32_t bh0[2] = {r4h[0], r4h[2]}, bh1[2] = {r4h[1], r4h[3]};
                uint32_t bl0[2] = {r4l[0], r4l[2]}, bl1[2] = {r4l[1], r4l[3]};
                #pragma unroll
                for (int mt = 0; mt < 2; mt++) {
                    mma16816(acc[mt][g*2],   ah[mt], bh0);
                    mma16816(acc[mt][g*2],   ah[mt], bl0);
                    mma16816(acc[mt][g*2],   al[mt], bh0);
                    mma16816(acc[mt][g*2+1], ah[mt], bh1);
                    mma16816(acc[mt][g*2+1], ah[mt], bl1);
                    mma16816(acc[mt][g*2+1], al[mt], bh1);
                }
            }
        }
        __syncthreads();
    }

    #pragma unroll
    for (int mt = 0; mt < 2; mt++) {
        int r0 = m0 + wm * 32 + mt * 16 + (lane >> 2);
        #pragma unroll
        for (int j = 0; j < 8; j++) {
            int c0 = n0 + wn * 64 + j * 8 + (lane & 3) * 2;
            #pragma unroll
            for (int e = 0; e < 4; e++)
                gemm_store(mz, r0 + (e >> 1) * 8, c0 + (e & 1), acc[mt][j][e],
                           mode, bias, resid, op);
        }
    }
#endif
}

// ---------------- fused FA2 flash attention (R11 + interleaved S MMAs) -------
#define ALD 72
#define QPLN (128 * ALD * 2)
#define KPLN (64 * ALD * 2)
#define STG  (3 * KPLN)              // Khi, Klo, V16
#define ATT_SMEM (2*QPLN + 2*STG)    // 92160

__device__ __forceinline__ void load_kv_stage(
        uint32_t stg, int kt, int tid,
        const __nv_bfloat16* khig, const __nv_bfloat16* klog,
        const __half* v16g) {
    #pragma unroll
    for (int i = 0; i < 2; i++) {
        int idx = i * 256 + tid;
        int r = idx >> 3, c8 = (idx & 7) * 8;
        size_t gofs = (size_t)(kt * 64 + r) * DD + c8;
        uint32_t so = (uint32_t)(r * ALD + c8) * 2;
        cpa16(stg + so,            khig + gofs);
        cpa16(stg + KPLN + so,     klog + gofs);
        cpa16(stg + 2 * KPLN + so, v16g + gofs);
    }
}

__global__ __launch_bounds__(256, 2) void attn_fused() {
    extern __shared__ char smraw[];
    __nv_bfloat16* sQh = (__nv_bfloat16*)smraw;
    __nv_bfloat16* sQl = sQh + 128 * ALD;
    uint32_t sb = smem_u32(smraw);

    int z = blockIdx.z, mz = z >> 1, b = z & 1;
    int h = blockIdx.y;
    int q0 = blockIdx.x * 128;
    int tid = threadIdx.x, wid = tid >> 5, lane = tid & 31;
    int rb = wid * 16;
    int tg = lane >> 2, tig = lane & 3;

    size_t hb = (size_t)mz * QSZ + (size_t)(b * HH + h) * NN * DD;
    const __nv_bfloat16* khig = g_khi + hb;
    const __nv_bfloat16* klog = g_klo + hb;
    const __half*        v16g = g_v16 + hb;

    #pragma unroll
    for (int i = 0; i < 4; i++) {
        int idx = i * 256 + tid;
        int r = idx >> 3, c8 = (idx & 7) * 8;
        size_t gq = hb + (size_t)(q0 + r) * DD + c8;
        *(uint4*)(sQh + r * ALD + c8) = *(const uint4*)(g_qhi + gq);
        *(uint4*)(sQl + r * ALD + c8) = *(const uint4*)(g_qlo + gq);
    }
    load_kv_stage(sb + 2 * QPLN, 0, tid, khig, klog, v16g);
    CP_COMMIT();
    __syncthreads();

    uint32_t qh[4][4];
    #pragma unroll
    for (int ks = 0; ks < 4; ks++)
        ldsm4(qh[ks], sb + ((rb + (lane & 15)) * ALD + ks * 16 + ((lane >> 4) * 8)) * 2);

    float o[8][4];
    #pragma unroll
    for (int g = 0; g < 8; g++)
        #pragma unroll
        for (int e = 0; e < 4; e++) o[g][e] = 0.f;
    float m0 = -1e30f, m1 = -1e30f, l0 = 0.f, l1 = 0.f;

    const int NT = NN / 64;
    for (int kt = 0; kt < NT; kt++) {
        uint32_t sk = sb + 2 * QPLN + (uint32_t)(kt & 1) * STG;
        if (kt + 1 < NT) {
            load_kv_stage(sb + 2 * QPLN + (uint32_t)((kt + 1) & 1) * STG,
                          kt + 1, tid, khig, klog, v16g);
            CP_COMMIT();
            CP_WAIT(1);
        } else {
            CP_WAIT(0);
        }
        __syncthreads();

        // ---- S = Q K^T (3-term split, accumulator-interleaved issue) ----
        float s[8][4];
        #pragma unroll
        for (int g = 0; g < 8; g++)
            #pragma unroll
            for (int e = 0; e < 4; e++) s[g][e] = 0.f;
        #pragma unroll
        for (int ks = 0; ks < 4; ks++) {
            uint32_t ql4[4];
            ldsm4(ql4, sb + QPLN + ((rb + (lane & 15)) * ALD + ks * 16 + ((lane >> 4) * 8)) * 2);
            #pragma unroll
            for (int nb = 0; nb < 4; nb++) {
                uint32_t r4h[4], r4l[4];
                uint32_t bd = sk + ((nb * 16 + (lane & 15)) * ALD + ks * 16 + ((lane >> 4) * 8)) * 2;
                ldsm4(r4h, bd);
                ldsm4(r4l, bd + KPLN);
                uint32_t bh0[2] = {r4h[0], r4h[2]}, bh1[2] = {r4h[1], r4h[3]};
                uint32_t bl0[2] = {r4l[0], r4l[2]}, bl1[2] = {r4l[1], r4l[3]};
                // alternate accumulators: same-acc dependency distance 2
                mma16816(s[nb*2],   qh[ks], bh0);
                mma16816(s[nb*2+1], qh[ks], bh1);
                mma16816(s[nb*2],   qh[ks], bl0);
                mma16816(s[nb*2+1], qh[ks], bl1);
                mma16816(s[nb*2],   ql4,    bh0);
                mma16816(s[nb*2+1], ql4,    bh1);
            }
        }

        float mx0 = -1e30f, mx1 = -1e30f;
        #pragma unroll
        for (int g = 0; g < 8; g++) {
            mx0 = fmaxf(mx0, fmaxf(s[g][0], s[g][1]));
            mx1 = fmaxf(mx1, fmaxf(s[g][2], s[g][3]));
        }
        mx0 = fmaxf(mx0, __shfl_xor_sync(0xffffffffu, mx0, 1));
        mx0 = fmaxf(mx0, __shfl_xor_sync(0xffffffffu, mx0, 2));
        mx1 = fmaxf(mx1, __shfl_xor_sync(0xffffffffu, mx1, 1));
        mx1 = fmaxf(mx1, __shfl_xor_sync(0xffffffffu, mx1, 2));
        float nm0 = fmaxf(m0, mx0), nm1 = fmaxf(m1, mx1);
        float a0 = ex2f(m0 - nm0), a1 = ex2f(m1 - nm1);
        m0 = nm0; m1 = nm1;

        uint32_t ph01[8], ph23[8];
        float sum0 = 0.f, sum1 = 0.f;
        #pragma unroll
        for (int g = 0; g < 8; g++) {
            float e0 = ex2f(s[g][0] - nm0), e1 = ex2f(s[g][1] - nm0);
            float e2 = ex2f(s[g][2] - nm1), e3 = ex2f(s[g][3] - nm1);
            sum0 += e0 + e1;  sum1 += e2 + e3;
            ph01[g] = cvth2(e1, e0);
            ph23[g] = cvth2(e3, e2);
        }
        sum0 += __shfl_xor_sync(0xffffffffu, sum0, 1);
        sum0 += __shfl_xor_sync(0xffffffffu, sum0, 2);
        sum1 += __shfl_xor_sync(0xffffffffu, sum1, 1);
        sum1 += __shfl_xor_sync(0xffffffffu, sum1, 2);
        l0 = l0 * a0 + sum0;
        l1 = l1 * a1 + sum1;
        #pragma unroll
        for (int g = 0; g < 8; g++) {
            o[g][0] *= a0; o[g][1] *= a0;
            o[g][2] *= a1; o[g][3] *= a1;
        }

        uint32_t sv = sk + 2 * KPLN;
        #pragma unroll
        for (int kg = 0; kg < 4; kg++) {
            uint32_t aph[4] = {ph01[2*kg], ph23[2*kg], ph01[2*kg+1], ph23[2*kg+1]};
            #pragma unroll
            for (int db = 0; db < 4; db++) {
                uint32_t r4[4];
                ldsm4t(r4, sv + ((kg * 16 + (lane & 15)) * ALD + db * 16 + ((lane >> 4) * 8)) * 2);
                uint32_t bh0[2] = {r4[0], r4[1]}, bh1[2] = {r4[2], r4[3]};
                mma16816h(o[db*2],   aph, bh0);
                mma16816h(o[db*2+1], aph, bh1);
            }
        }
        __syncthreads();
    }

    float inv0 = 1.0f / l0, inv1 = 1.0f / l1;
    int rr0 = q0 + rb + tg;
    size_t mofs = (size_t)mz * MM * EE;
    #pragma unroll
    for (int g = 0; g < 8; g++) {
        int dd = g * 8 + tig * 2;
        size_t o0 = mofs + ((size_t)b * NN + rr0) * EE + h * DD + dd;
        split_st(g_att_hi, g_att_lo, o0,     o[g][0] * inv0);
        split_st(g_att_hi, g_att_lo, o0 + 1, o[g][1] * inv0);
        size_t o8 = o0 + (size_t)8 * EE;
        split_st(g_att_hi, g_att_lo, o8,     o[g][2] * inv1);
        split_st(g_att_hi, g_att_lo, o8 + 1, o[g][3] * inv1);
    }
}

// ---------------- launch -----------------------------------------------------
extern "C" void kernel_launch(void* const* d_in, const int* in_sizes, int n_in,
                              void* d_out, int out_size) {
    const float* in[14];
    for (int i = 0; i < 14; i++) in[i] = (const float*)d_in[i];
    float* out = (float*)d_out;

    cudaFuncSetAttribute(gemm_fused,
                         cudaFuncAttributeMaxDynamicSharedMemorySize, GEMM_SMEM_HOST);
    cudaFuncSetAttribute(attn_fused,
                         cudaFuncAttributeMaxDynamicSharedMemorySize, ATT_SMEM);

    pre_fused<<<2 * MM + SPLIT_BLOCKS, 256>>>(
        in[0], in[1], in[2], in[3], in[8], in[9],
        in[4], in[6], in[10], in[12]);
    gemm_fused<<<dim3(E3 / 128, MM / 128, 2), 256, GEMM_SMEM_HOST>>>(
        in[5], in[11], nullptr, nullptr, nullptr, 0);
    attn_fused<<<dim3(NN / 128, HH, 2 * BB), 256, ATT_SMEM>>>();
    gemm_fused<<<dim3(EE / 128, MM / 128, 2), 256, GEMM_SMEM_HOST>>>(
        in[7], in[13], in[0], in[1], out, 1);
}